// round 6
// baseline (speedup 1.0000x reference)
#include <cuda_runtime.h>
#include <cuda_bf16.h>

// PointMatcher: pred (N=1024,20,2) vs gt (M=2048,20,2)
// dist(i,j) = mean_p ||pred[i,p]-gt[j,p]|| ; argmin over j per i.
// Outputs concatenated in d_out (float32):
//   [0..N*40) matched gt rows | [N*40..N*41) confidence | [N*41..N*42) indices

#define BI      4       // pred rows per block
#define TJ      256     // gt rows per tile
#define HJ      128     // row split: thread handles rows jl and jl+HJ
#define P       20
#define ROWF    40      // floats per row
#define ROWP    44      // padded shared stride; 176B*jl mod 128 covers all banks
#define THREADS 512
#define TILEF   (TJ * ROWP)                  // floats per buffer (11264)
#define SMEM_BYTES (2*TILEF*4 + BI*P*8 + BI*8)

typedef unsigned long long ull;

__device__ __forceinline__ float fsqrt_approx(float x) {
    float r;
    asm("sqrt.approx.f32 %0, %1;" : "=f"(r) : "f"(x));
    return r;
}
__device__ __forceinline__ void cp_async16(float* dst, const float* src) {
    unsigned sa = (unsigned)__cvta_generic_to_shared(dst);
    asm volatile("cp.async.cg.shared.global [%0], [%1], 16;" :: "r"(sa), "l"(src));
}
// one packed diff-square-sum-sqrt: returns sqrt((gx-px)^2+(gy-py)^2), packed ops
__device__ __forceinline__ float pair_dist(ull g, ull pneg) {
    ull d, q;
    asm("add.rn.f32x2 %0, %1, %2;" : "=l"(d) : "l"(g), "l"(pneg));
    asm("mul.rn.f32x2 %0, %1, %2;" : "=l"(q) : "l"(d), "l"(d));
    float a, b;
    asm("mov.b64 {%0,%1}, %2;" : "=f"(a), "=f"(b) : "l"(q));
    return fsqrt_approx(a + b);
}

__global__ __launch_bounds__(THREADS, 2)
void pointmatcher_kernel(const float* __restrict__ pred,
                         const float* __restrict__ gt,
                         float* __restrict__ out_mp,
                         float* __restrict__ out_conf,
                         float* __restrict__ out_idx,
                         int N, int M)
{
    extern __shared__ float smem[];
    float* buf[2] = { smem, smem + TILEF };
    ull*   spred  = (ull*)(smem + 2 * TILEF);      // [BI][P] packed {-x,-y}
    ull*   best   = (ull*)(spred + BI * P);

    const int tid = threadIdx.x;
    const int il  = tid & (BI - 1);
    const int jl  = tid >> 2;                      // 0..127 -> rows jl, jl+HJ

    if (tid < BI) best[tid] = ~0ull;
    if (tid < BI * P) {                            // pre-negated packed pred
        int pi = tid / P, pp = tid - pi * P;
        float2 v = ((const float2*)(pred + (size_t)(blockIdx.x * BI + pi) * ROWF))[pp];
        float nx = -v.x, ny = -v.y;
        ull pk;
        asm("mov.b64 %0, {%1,%2};" : "=l"(pk) : "f"(nx), "f"(ny));
        spred[tid] = pk;
    }

    // prefetch tile 0
    {
        #pragma unroll
        for (int it = 0; it < 5; it++) {
            int f = tid + it * THREADS;            // float4 index 0..2559
            int row = f / 10, k4 = f - row * 10;
            cp_async16(buf[0] + row * ROWP + k4 * 4, gt + f * 4);
        }
        asm volatile("cp.async.commit_group;");
    }

    float minv = 3.402823466e+38f;                 // min of SUM (mean deferred)
    int   minj = 0;
    const int ntiles = M / TJ;                     // 8

    for (int t = 0; t < ntiles; t++) {
        asm volatile("cp.async.wait_group 0;");
        __syncthreads();

        if (t + 1 < ntiles) {
            const float* src = gt + (size_t)(t + 1) * TJ * ROWF;
            float* dst = buf[(t + 1) & 1];
            #pragma unroll
            for (int it = 0; it < 5; it++) {
                int f = tid + it * THREADS;
                int row = f / 10, k4 = f - row * 10;
                cp_async16(dst + row * ROWP + k4 * 4, src + f * 4);
            }
        }
        asm volatile("cp.async.commit_group;");

        // 128-bit shared reads: 2 points per load, conflict-free layout.
        const ulonglong2* t0 = (const ulonglong2*)(buf[t & 1] + jl * ROWP);
        const ulonglong2* t1 = (const ulonglong2*)(buf[t & 1] + (jl + HJ) * ROWP);
        const ulonglong2* pn = (const ulonglong2*)(spred + il * P);

        float sum0 = 0.f, sum1 = 0.f;
        #pragma unroll
        for (int k = 0; k < P / 2; k++) {
            ulonglong2 g0 = t0[k];                 // points 2k,2k+1 of row jl
            ulonglong2 g1 = t1[k];                 // points 2k,2k+1 of row jl+HJ
            ulonglong2 pk = pn[k];                 // negated pred points
            sum0 += pair_dist(g0.x, pk.x);
            sum0 += pair_dist(g0.y, pk.y);
            sum1 += pair_dist(g1.x, pk.x);
            sum1 += pair_dist(g1.y, pk.y);
        }
        int j0 = t * TJ + jl;
        int j1 = t * TJ + jl + HJ;
        if (sum0 < minv) { minv = sum0; minj = j0; }  // ascending j per thread:
        if (sum1 < minv) { minv = sum1; minj = j1; }  // '<' keeps first tie
    }

    // Block argmin: packed (dist_bits, j); min == (min dist, then min j).
    ull key = ((ull)__float_as_uint(minv) << 32) | (unsigned)minj;
    atomicMin(&best[il], key);
    __syncthreads();

    if (tid < BI) {
        ull b = best[tid];
        int j = (int)(unsigned)b;
        float md = __uint_as_float((unsigned)(b >> 32)) * (1.0f / (float)P);
        int row = blockIdx.x * BI + tid;
        out_conf[row] = (md > 2.0f) ? 0.0f : expf(-md);
        out_idx[row]  = (float)j;
    }
    if (tid < BI * ROWF) {
        int ilg = tid / ROWF;
        int k   = tid - ilg * ROWF;
        int j   = (int)(unsigned)best[ilg];
        out_mp[(blockIdx.x * BI + ilg) * ROWF + k] = gt[(size_t)j * ROWF + k];
    }
}

extern "C" void kernel_launch(void* const* d_in, const int* in_sizes, int n_in,
                              void* d_out, int out_size)
{
    const float* pred = (const float*)d_in[0];
    const float* gt   = (const float*)d_in[1];
    float* out        = (float*)d_out;

    int N = in_sizes[0] / ROWF;   // 1024
    int M = in_sizes[1] / ROWF;   // 2048

    float* out_mp   = out;
    float* out_conf = out + (size_t)N * ROWF;
    float* out_idx  = out + (size_t)N * ROWF + N;

    static bool attr_set = false;  // host-side only; not in the captured graph
    if (!attr_set) {
        cudaFuncSetAttribute(pointmatcher_kernel,
                             cudaFuncAttributeMaxDynamicSharedMemorySize,
                             SMEM_BYTES);
        attr_set = true;
    }

    pointmatcher_kernel<<<N / BI, THREADS, SMEM_BYTES>>>(
        pred, gt, out_mp, out_conf, out_idx, N, M);
}